// round 6
// baseline (speedup 1.0000x reference)
#include <cuda_runtime.h>
#include <float.h>

#define B_IMG 2
#define N_BOX 20000
#define C_CLS 80
#define BC (B_IMG * C_CLS)          // 160
#define KCAP 1024                   // smem candidate cap (mean ~400, 30 sigma)
#define MAXV 512                    // fast-path NMS limit; slow fallback beyond
#define WMAX (MAXV / 32)            // 16
#define PRE_K 1000
#define MAX_DET 300
#define SCORE_THR 0.05f
#define IOU_THR 0.5f
#define WIN 64
#define NB 2048
#define CCAP 2048
#define GRID 160
#define TPB 512
#define SMEM_BYTES 51200

// ---------------- scratch (no allocations allowed) ----------------
__device__ int   g_done, g_done2;   // finisher tickets (start 0, self-resetting)
__device__ int   g_keep_count[BC];
__device__ float g_keep_score[BC * MAX_DET];
__device__ int   g_keep_idx[BC * MAX_DET];

// block-parallel suffix-scan bucket finder (512 threads)
__device__ __forceinline__ void find_cross(const int* hist, int nb, int rem,
                                           int tid, int* scan, int* res) {
    int chunk = nb / TPB;
    int base = tid * chunk;
    int lsum = 0;
    for (int k = 0; k < chunk; k++) lsum += hist[base + k];
    scan[tid] = lsum;
    __syncthreads();
    for (int off = 1; off < TPB; off <<= 1) {
        int v = (tid + off < TPB) ? scan[tid + off] : 0;
        __syncthreads();
        scan[tid] += v;
        __syncthreads();
    }
    int incl = scan[tid];
    int total = scan[0];
    if (tid == 0 && total < rem) { res[0] = -1; res[1] = total; }
    if (total >= rem) {
        int after = incl - lsum;
        if (after < rem && rem <= incl) {
            int cum = after;
            for (int k = chunk - 1; k >= 0; k--) {
                int h = hist[base + k];
                cum += h;
                if (cum >= rem) { res[0] = base + k; res[1] = cum - h; break; }
            }
        }
    }
}

__global__ __launch_bounds__(TPB)
void fused_kernel(const float* __restrict__ boxes,
                  const float* __restrict__ cls,
                  const float* __restrict__ cen,
                  float* __restrict__ out) {
    extern __shared__ unsigned char dynbuf[];
    unsigned long long* s_key = (unsigned long long*)dynbuf;          // KCAP
    float4*   s_box  = (float4*)(s_key + KCAP);                       // MAXV
    unsigned* s_mask = (unsigned*)(s_box + MAXV);                     // MAXV*WMAX
    int*      s_any  = (int*)(s_mask + MAXV * WMAX);                  // MAXV
    __shared__ int s_cnt, s_ticket;

    const int tid = threadIdx.x;
    const int bc  = blockIdx.x;
    const int b   = bc / C_CLS;
    const int c   = bc % C_CLS;

    if (tid == 0) s_cnt = 0;
    __syncthreads();

    // ===== phase 1: gather this block's class column, compact into SMEM =====
    {
        const float* col  = cls + (size_t)b * N_BOX * C_CLS + c;
        const float* cenb = cen + b * N_BOX;
        for (int n = tid; n < N_BOX; n += TPB) {
            float raw = __ldg(col + (size_t)n * C_CLS);
            if (raw > SCORE_THR) {
                float s = sqrtf(raw * cenb[n]);
                int pos = atomicAdd(&s_cnt, 1);
                if (pos < KCAP)
                    s_key[pos] = ((unsigned long long)__float_as_uint(s) << 32)
                               | (unsigned)(~(unsigned)n);
            }
        }
    }
    __syncthreads();

    int V = s_cnt < KCAP ? s_cnt : KCAP;
    int M = 1;
    while (M < V) M <<= 1;
    for (int i = V + tid; i < M; i += TPB) s_key[i] = 0ull;
    __syncthreads();

    // ===== phase 2a: bitonic sort (desc score, tie -> smaller idx) =====
    if (M <= TPB) {
        // hybrid: j<32 stages via register shfl, j>=32 via smem
        unsigned long long key = (tid < M) ? s_key[tid] : 0ull;
        int kreg = M < 32 ? M : 32;
        for (int k = 2; k <= kreg; k <<= 1) {
            bool up_k = ((tid & k) == 0);
            for (int j = k >> 1; j > 0; j >>= 1) {
                unsigned long long oth = __shfl_xor_sync(0xffffffffu, key, j);
                bool lower = ((tid & j) == 0);
                bool take_max = (up_k == lower);
                key = take_max ? (key > oth ? key : oth) : (key < oth ? key : oth);
            }
        }
        for (int k = 64; k <= M; k <<= 1) {
            if (tid < M) s_key[tid] = key;
            __syncthreads();
            for (int j = k >> 1; j >= 32; j >>= 1) {
                int ixj = tid ^ j;
                if (tid < M && ixj > tid) {
                    unsigned long long a = s_key[tid], d = s_key[ixj];
                    bool up = ((tid & k) == 0);
                    if (up ? (a < d) : (a > d)) { s_key[tid] = d; s_key[ixj] = a; }
                }
                __syncthreads();
            }
            key = (tid < M) ? s_key[tid] : 0ull;
            bool up_k = ((tid & k) == 0);
            for (int j = 16; j > 0; j >>= 1) {
                unsigned long long oth = __shfl_xor_sync(0xffffffffu, key, j);
                bool lower = ((tid & j) == 0);
                bool take_max = (up_k == lower);
                key = take_max ? (key > oth ? key : oth) : (key < oth ? key : oth);
            }
        }
        if (tid < M) s_key[tid] = key;
        __syncthreads();
    } else {
        for (int k = 2; k <= M; k <<= 1) {
            for (int j = k >> 1; j > 0; j >>= 1) {
                for (int i = tid; i < M; i += TPB) {
                    int ixj = i ^ j;
                    if (ixj > i) {
                        unsigned long long a = s_key[i], d = s_key[ixj];
                        bool up = ((i & k) == 0);
                        if (up ? (a < d) : (a > d)) { s_key[i] = d; s_key[ixj] = a; }
                    }
                }
                __syncthreads();
            }
        }
    }

    int K_eff = V < PRE_K ? V : PRE_K;

    // ===== phase 2b: NMS =====
    if (V <= MAXV) {
        for (int i = tid; i < K_eff; i += TPB) {
            int n = (int)(~((unsigned)s_key[i]));
            s_box[i] = reinterpret_cast<const float4*>(boxes)[b * N_BOX + n];
            s_any[i] = 0;
        }
        __syncthreads();

        int W = (K_eff + 31) >> 5;
        for (int t = tid; t < K_eff * W; t += TPB) {
            int i = t / W, w = t % W;
            unsigned m = 0;
            int jb = w << 5;
            if (jb + 31 > i) {
                float4 bi = s_box[i];
                float ai = (bi.z - bi.x) * (bi.w - bi.y);
                int jend = min(jb + 32, K_eff);
                for (int j = max(jb, i + 1); j < jend; j++) {
                    float4 bj = s_box[j];
                    float w_ = fmaxf(fminf(bi.z, bj.z) - fmaxf(bi.x, bj.x), 0.0f);
                    float h_ = fmaxf(fminf(bi.w, bj.w) - fmaxf(bi.y, bj.y), 0.0f);
                    float inter = w_ * h_;
                    float uni = ai + (bj.z - bj.x) * (bj.w - bj.y) - inter;
                    if (inter / fmaxf(uni, 1e-8f) > IOU_THR) m |= 1u << (j - jb);
                }
                if (m) s_any[i] = 1;
            }
            s_mask[t] = m;
        }
        __syncthreads();

        if (tid < 32) {
            // chunked serial sweep: 1 shfl per 32 candidates + per-keep row OR
            unsigned sup = 0;       // lane l holds suppressed bits for [32l,32l+32)
            int nk = 0;
            int nchunk = (K_eff + 31) >> 5;
            for (int g = 0; g < nchunk && nk < MAX_DET; g++) {
                unsigned ow = __shfl_sync(0xffffffffu, sup, g);
                int bend = min(32, K_eff - (g << 5));
                for (int bb2 = 0; bb2 < bend; bb2++) {
                    if (!(ow & (1u << bb2))) {
                        int i = (g << 5) + bb2;
                        if (tid == 0) {
                            unsigned long long kk = s_key[i];
                            g_keep_score[bc * MAX_DET + nk] = __uint_as_float((unsigned)(kk >> 32));
                            g_keep_idx[bc * MAX_DET + nk]   = (int)(~((unsigned)kk));
                        }
                        unsigned m = (tid < W && s_any[i]) ? s_mask[i * W + tid] : 0u;
                        sup |= m;
                        ow  |= __shfl_sync(0xffffffffu, m, g);
                        nk++;
                        if (nk >= MAX_DET) break;
                    }
                }
            }
            if (tid == 0) g_keep_count[bc] = nk;
        }
    } else {
        // slow fallback: barrier greedy, boxes from global
        unsigned char* sup = (unsigned char*)s_mask;
        __shared__ int s_nk;
        for (int i = tid; i < K_eff; i += TPB) sup[i] = 0;
        if (tid == 0) s_nk = 0;
        __syncthreads();
        for (int i = 0; i < K_eff; i++) {
            if (!sup[i]) {
                unsigned long long ki = s_key[i];
                int ni = (int)(~((unsigned)ki));
                if (tid == 0) {
                    int nk = s_nk;
                    g_keep_score[bc * MAX_DET + nk] = __uint_as_float((unsigned)(ki >> 32));
                    g_keep_idx[bc * MAX_DET + nk]   = ni;
                    s_nk = nk + 1;
                }
                float4 bi = reinterpret_cast<const float4*>(boxes)[b * N_BOX + ni];
                float ai = (bi.z - bi.x) * (bi.w - bi.y);
                for (int j = i + 1 + tid; j < K_eff; j += TPB) {
                    if (!sup[j]) {
                        int nj = (int)(~((unsigned)s_key[j]));
                        float4 bj = reinterpret_cast<const float4*>(boxes)[b * N_BOX + nj];
                        float aj = (bj.z - bj.x) * (bj.w - bj.y);
                        float w_ = fmaxf(fminf(bi.z, bj.z) - fmaxf(bi.x, bj.x), 0.0f);
                        float h_ = fmaxf(fminf(bi.w, bj.w) - fmaxf(bi.y, bj.y), 0.0f);
                        float inter = w_ * h_;
                        float uni = ai + aj - inter;
                        if (inter / fmaxf(uni, 1e-8f) > IOU_THR) sup[j] = 1;
                    }
                }
                __syncthreads();
                if (s_nk >= MAX_DET) break;
            }
        }
        if (tid == 0) g_keep_count[bc] = (s_nk <= MAX_DET) ? s_nk : MAX_DET;
    }

    // ===== finisher ticket: last B_IMG finishers run the merge =====
    __threadfence();
    __syncthreads();
    if (tid == 0) s_ticket = atomicAdd(&g_done, 1);
    __syncthreads();
    int ticket = s_ticket;
    if (ticket < GRID - B_IMG) return;
    const int img = ticket - (GRID - B_IMG);
    if (tid == 0) {
        while (*(volatile int*)&g_done < GRID) {}   // passes immediately by construction
        int r = atomicAdd(&g_done2, 1);
        if (r == B_IMG - 1) { g_done = 0; g_done2 = 0; }   // reset for next replay
    }
    __syncthreads();
    __threadfence();

    // ===== phase 3: per-image radix-select top-300 (truncated + exact fallback) =====
    {
        unsigned* s_u   = (unsigned*)dynbuf;                        // C_CLS*WIN
        int*      hist  = (int*)(s_u + C_CLS * WIN);                // NB
        int*      scan  = hist + NB;                                // TPB
        int*      s_ccnt = scan + TPB;                              // C_CLS
        unsigned long long* s_k3 = (unsigned long long*)(s_ccnt + C_CLS); // CCAP
        __shared__ int s_res[2];
        __shared__ int s_ncoll;
        __shared__ unsigned s_maxtr;

        if (tid < C_CLS) s_ccnt[tid] = g_keep_count[img * C_CLS + tid];
        if (tid == 0) { s_maxtr = 0; s_ncoll = 0; }
        __syncthreads();
        if (tid < C_CLS && s_ccnt[tid] > WIN)
            atomicMax(&s_maxtr, __float_as_uint(g_keep_score[(img * C_CLS + tid) * MAX_DET + WIN]));
        __syncthreads();

        unsigned Tu = 0;
        bool found = false;
        int win = WIN, pool = C_CLS * WIN, fmode = 0;

        for (int mode = 0; mode < 2; mode++) {
            win = mode ? MAX_DET : WIN;
            pool = C_CLS * win;
            fmode = mode;

            for (int i = tid; i < 1024; i += TPB) hist[i] = 0;
            __syncthreads();
            for (int t = tid; t < pool; t += TPB) {
                int cc = t / win, r = t % win;
                unsigned u = (r < s_ccnt[cc])
                           ? __float_as_uint(g_keep_score[(img * C_CLS + cc) * MAX_DET + r]) : 0;
                if (!mode) s_u[t] = u;
                if (u) atomicAdd(&hist[u >> 22], 1);
            }
            __syncthreads();
            find_cross(hist, 1024, MAX_DET, tid, scan, s_res);
            __syncthreads();
            int b1 = s_res[0], na1 = s_res[1];
            found = (b1 >= 0);
            Tu = 0;

            if (found) {
                for (int i = tid; i < NB; i += TPB) hist[i] = 0;
                __syncthreads();
                for (int t = tid; t < pool; t += TPB) {
                    unsigned u;
                    if (!mode) u = s_u[t];
                    else {
                        int cc = t / win, r = t % win;
                        u = (r < s_ccnt[cc])
                          ? __float_as_uint(g_keep_score[(img * C_CLS + cc) * MAX_DET + r]) : 0;
                    }
                    if (u && (int)(u >> 22) == b1) atomicAdd(&hist[(u >> 11) & 0x7FF], 1);
                }
                __syncthreads();
                find_cross(hist, 2048, MAX_DET - na1, tid, scan, s_res);
                __syncthreads();
                int b2 = s_res[0], na2 = s_res[1];
                unsigned p2 = ((unsigned)b1 << 11) | (unsigned)b2;

                for (int i = tid; i < NB; i += TPB) hist[i] = 0;
                __syncthreads();
                for (int t = tid; t < pool; t += TPB) {
                    unsigned u;
                    if (!mode) u = s_u[t];
                    else {
                        int cc = t / win, r = t % win;
                        u = (r < s_ccnt[cc])
                          ? __float_as_uint(g_keep_score[(img * C_CLS + cc) * MAX_DET + r]) : 0;
                    }
                    if (u && (u >> 11) == p2) atomicAdd(&hist[u & 0x7FF], 1);
                }
                __syncthreads();
                find_cross(hist, 2048, MAX_DET - na1 - na2, tid, scan, s_res);
                __syncthreads();
                Tu = (p2 << 11) | (unsigned)s_res[0];
            }
            __syncthreads();

            if (mode == 0) {
                bool valid = found ? (Tu > s_maxtr) : (s_maxtr == 0);
                if (valid) break;
            }
        }

        for (int t = tid; t < pool; t += TPB) {
            unsigned u;
            int cc = t / win, r = t % win;
            if (!fmode) u = s_u[t];
            else u = (r < s_ccnt[cc])
                   ? __float_as_uint(g_keep_score[(img * C_CLS + cc) * MAX_DET + r]) : 0;
            if (u && (!found || u >= Tu)) {
                int pos = atomicAdd(&s_ncoll, 1);
                if (pos < CCAP) {
                    int flat = cc * MAX_DET + r;
                    s_k3[pos] = ((unsigned long long)u << 16) | (unsigned)(0xFFFF - flat);
                }
            }
        }
        __syncthreads();
        int Ncoll = s_ncoll < CCAP ? s_ncoll : CCAP;
        int M2 = 1;
        while (M2 < Ncoll) M2 <<= 1;
        for (int i = tid; i < M2; i += TPB) if (i >= Ncoll) s_k3[i] = 0ull;
        __syncthreads();

        for (int k = 2; k <= M2; k <<= 1) {
            for (int j = k >> 1; j > 0; j >>= 1) {
                for (int i = tid; i < M2; i += TPB) {
                    int ixj = i ^ j;
                    if (ixj > i) {
                        unsigned long long a = s_k3[i], d = s_k3[ixj];
                        bool up = ((i & k) == 0);
                        if (up ? (a < d) : (a > d)) { s_k3[i] = d; s_k3[ixj] = a; }
                    }
                }
                __syncthreads();
            }
        }

        if (tid < MAX_DET) {
            float* fb = out + img * (MAX_DET * 4) + tid * 4;
            float* fs = out + B_IMG * MAX_DET * 4 + img * MAX_DET + tid;
            float* fl = out + B_IMG * MAX_DET * 4 + B_IMG * MAX_DET + img * MAX_DET + tid;
            if (tid < Ncoll) {
                unsigned long long kk = s_k3[tid];
                unsigned u = (unsigned)(kk >> 16);
                int flat = 0xFFFF - (int)(kk & 0xFFFF);
                int cc = flat / MAX_DET, r = flat % MAX_DET;
                int n = g_keep_idx[(img * C_CLS + cc) * MAX_DET + r];
                float4 bb = reinterpret_cast<const float4*>(boxes)[img * N_BOX + n];
                fb[0] = bb.x; fb[1] = bb.y; fb[2] = bb.z; fb[3] = bb.w;
                *fs = __uint_as_float(u);
                *fl = (float)cc;
            } else {
                fb[0] = -1.0f; fb[1] = -1.0f; fb[2] = -1.0f; fb[3] = -1.0f;
                *fs = -1.0f; *fl = -1.0f;
            }
        }
    }
}

// ---------------- host launcher ----------------
extern "C" void kernel_launch(void* const* d_in, const int* in_sizes, int n_in,
                              void* d_out, int out_size) {
    const float* boxes = (const float*)d_in[0];           // [2,20000,4]
    const float* cls   = (const float*)d_in[1];           // [2,20000,80]
    const float* cen   = (const float*)d_in[2];           // [2,20000,1]
    float* out = (float*)d_out;                           // fb(2400) | fs(600) | fl(600)

    cudaFuncSetAttribute(fused_kernel,
                         cudaFuncAttributeMaxDynamicSharedMemorySize, SMEM_BYTES);

    fused_kernel<<<GRID, TPB, SMEM_BYTES>>>(boxes, cls, cen, out);
}

// round 7
// speedup vs baseline: 2.0855x; 2.0855x over previous
#include <cuda_runtime.h>
#include <float.h>

#define B_IMG 2
#define N_BOX 20000
#define C_CLS 80
#define BC (B_IMG * C_CLS)          // 160
#define CAP 1024                    // global candidate cap per (b,c)
#define CPAD 32                     // counter padding (128B stride)
#define MAXV 512                    // fast-path NMS limit; slow fallback beyond
#define WMAX (MAXV / 32)            // 16
#define PRE_K 1000
#define MAX_DET 300
#define SCORE_THR 0.05f
#define IOU_THR 0.5f
#define WIN 64
#define NB 2048
#define CCAP 2048
#define GRID 160
#define TPB 512
#define SMEM_BYTES 67584

// ---------------- scratch (no allocations allowed) ----------------
__device__ int   g_b1, g_done, g_done2;      // barrier + finisher tickets (start 0, self-reset)
__device__ int   g_cand_count[BC * CPAD];
__device__ float g_cand_score[BC * CAP];
__device__ int   g_cand_idx[BC * CAP];
__device__ int   g_keep_count[BC];
__device__ float g_keep_score[BC * MAX_DET];
__device__ int   g_keep_idx[BC * MAX_DET];

// ---- descending bitonic sort of M (pow2) 64-bit keys; hybrid shfl/smem ----
__device__ __forceinline__ void bitonic_desc(unsigned long long* sk, int M, int tid) {
    if (M <= 1) return;
    if (M <= TPB) {
        unsigned long long key = (tid < M) ? sk[tid] : 0ull;
        int kreg = M < 32 ? M : 32;
        for (int k = 2; k <= kreg; k <<= 1) {
            bool up_k = ((tid & k) == 0);
            for (int j = k >> 1; j > 0; j >>= 1) {
                unsigned long long oth = __shfl_xor_sync(0xffffffffu, key, j);
                bool lower = ((tid & j) == 0);
                bool take_max = (up_k == lower);
                key = take_max ? (key > oth ? key : oth) : (key < oth ? key : oth);
            }
        }
        for (int k = 64; k <= M; k <<= 1) {
            if (tid < M) sk[tid] = key;
            __syncthreads();
            for (int j = k >> 1; j >= 32; j >>= 1) {
                int ixj = tid ^ j;
                if (tid < M && ixj > tid) {
                    unsigned long long a = sk[tid], d = sk[ixj];
                    bool up = ((tid & k) == 0);
                    if (up ? (a < d) : (a > d)) { sk[tid] = d; sk[ixj] = a; }
                }
                __syncthreads();
            }
            key = (tid < M) ? sk[tid] : 0ull;
            bool up_k = ((tid & k) == 0);
            for (int j = 16; j > 0; j >>= 1) {
                unsigned long long oth = __shfl_xor_sync(0xffffffffu, key, j);
                bool lower = ((tid & j) == 0);
                bool take_max = (up_k == lower);
                key = take_max ? (key > oth ? key : oth) : (key < oth ? key : oth);
            }
        }
        if (tid < M) sk[tid] = key;
        __syncthreads();
    } else {
        for (int k = 2; k <= M; k <<= 1) {
            for (int j = k >> 1; j > 0; j >>= 1) {
                for (int i = tid; i < M; i += TPB) {
                    int ixj = i ^ j;
                    if (ixj > i) {
                        unsigned long long a = sk[i], d = sk[ixj];
                        bool up = ((i & k) == 0);
                        if (up ? (a < d) : (a > d)) { sk[i] = d; sk[ixj] = a; }
                    }
                }
                __syncthreads();
            }
        }
    }
}

// ---- block-parallel suffix-scan bucket finder ----
__device__ __forceinline__ void find_cross(const int* hist, int nb, int rem,
                                           int tid, int* scan, int* res) {
    int chunk = nb / TPB;
    int base = tid * chunk;
    int lsum = 0;
    for (int k = 0; k < chunk; k++) lsum += hist[base + k];
    scan[tid] = lsum;
    __syncthreads();
    for (int off = 1; off < TPB; off <<= 1) {
        int v = (tid + off < TPB) ? scan[tid + off] : 0;
        __syncthreads();
        scan[tid] += v;
        __syncthreads();
    }
    int incl = scan[tid];
    int total = scan[0];
    if (tid == 0 && total < rem) { res[0] = -1; res[1] = total; }
    if (total >= rem) {
        int after = incl - lsum;
        if (after < rem && rem <= incl) {
            int cum = after;
            for (int k = chunk - 1; k >= 0; k--) {
                int h = hist[base + k];
                cum += h;
                if (cum >= rem) { res[0] = base + k; res[1] = cum - h; break; }
            }
        }
    }
}

__global__ __launch_bounds__(TPB)
void fused_kernel(const float* __restrict__ boxes,
                  const float4* __restrict__ cls4,
                  const float* __restrict__ cen,
                  float* __restrict__ out) {
    extern __shared__ unsigned char dynbuf[];
    // phase-2 layout
    unsigned long long* s_key  = (unsigned long long*)dynbuf;            // CAP (8KB)
    float4*             s_box  = (float4*)(dynbuf + 8192);               // MAXV (8KB)
    unsigned long long* s_xkey = (unsigned long long*)(dynbuf + 16384);  // MAXV (4KB)
    float*              sx1    = (float*)(dynbuf + 20480);               // MAXV (2KB)
    float4*             s_f4   = (float4*)(dynbuf + 22528);              // MAXV (8KB)
    int*                srank  = (int*)(dynbuf + 30720);                 // MAXV (2KB)
    unsigned*           s_mask = (unsigned*)(dynbuf + 32768);            // MAXV*WMAX (32KB)
    int*                s_any  = (int*)(dynbuf + 65536);                 // MAXV (2KB)
    __shared__ int s_ticket;

    const int tid = threadIdx.x;
    const int bc  = blockIdx.x;
    const int b   = bc / C_CLS;

    // ===== phase 1: coalesced threshold + compact to global =====
    {
        const int total4 = B_IMG * N_BOX * C_CLS / 4;
        for (int q = bc * TPB + tid; q < total4; q += GRID * TPB) {
            float4 v = cls4[q];
            if (v.x > SCORE_THR || v.y > SCORE_THR || v.z > SCORE_THR || v.w > SCORE_THR) {
                int base = q * 4;
                int c0  = base % C_CLS;          // 80 % 4 == 0: all 4 share (b,n)
                int rem = base / C_CLS;          // = b*N_BOX + n
                int bb  = rem / N_BOX;
                float ce = cen[rem];
                float vv[4] = {v.x, v.y, v.z, v.w};
                #pragma unroll
                for (int k = 0; k < 4; k++) {
                    if (vv[k] > SCORE_THR) {
                        float s = sqrtf(vv[k] * ce);
                        int idx = bb * C_CLS + c0 + k;
                        int pos = atomicAdd(&g_cand_count[idx * CPAD], 1);
                        if (pos < CAP) {
                            g_cand_score[idx * CAP + pos] = s;
                            g_cand_idx[idx * CAP + pos]   = rem % N_BOX;
                        }
                    }
                }
            }
        }
    }

    // ---- grid barrier 1 (all 160 blocks co-resident: <=2 blks/SM by regs/smem) ----
    __threadfence();
    __syncthreads();
    if (tid == 0) {
        atomicAdd(&g_b1, 1);
        while (*(volatile int*)&g_b1 < GRID) {}
    }
    __syncthreads();
    __threadfence();

    // ===== phase 2: score sort + x-sweep NMS =====
    int V = g_cand_count[bc * CPAD];
    if (V > CAP) V = CAP;
    {
        int M = 1;
        while (M < V) M <<= 1;

        for (int i = tid; i < M; i += TPB) {
            if (i < V) {
                unsigned sb = __float_as_uint(g_cand_score[bc * CAP + i]);
                unsigned ix = (unsigned)g_cand_idx[bc * CAP + i];
                s_key[i] = ((unsigned long long)sb << 32) | (unsigned)(~ix);
            } else {
                s_key[i] = 0ull;
            }
        }
        __syncthreads();
        if (tid == 0) g_cand_count[bc * CPAD] = 0;   // re-zero for next replay

        bitonic_desc(s_key, M, tid);                 // score desc, tie -> smaller idx

        int K_eff = V < PRE_K ? V : PRE_K;

        if (V <= MAXV) {
            // gather boxes in score order
            for (int i = tid; i < V; i += TPB) {
                int n = (int)(~((unsigned)s_key[i]));
                s_box[i] = reinterpret_cast<const float4*>(boxes)[b * N_BOX + n];
            }
            // zero mask + any
            for (int t = tid; t < V * WMAX; t += TPB) s_mask[t] = 0u;
            for (int i = tid; i < V; i += TPB) s_any[i] = 0;
            __syncthreads();

            // x-sort keys: descending on ~x1bits -> ascending x1; payload = score rank
            int Mx = M <= MAXV ? M : MAXV;
            for (int i = tid; i < Mx; i += TPB) {
                s_xkey[i] = (i < V)
                    ? ((unsigned long long)(~__float_as_uint(s_box[i].x)) << 32) | (unsigned)i
                    : 0ull;
            }
            __syncthreads();
            bitonic_desc(s_xkey, Mx, tid);

            // build x-order SoA
            for (int p = tid; p < V; p += TPB) {
                int r = (int)(unsigned)s_xkey[p];
                float4 bb4 = s_box[r];
                sx1[p] = bb4.x;
                s_f4[p] = make_float4(bb4.z, bb4.y, bb4.w,
                                      (bb4.z - bb4.x) * (bb4.w - bb4.y));
                srank[p] = r;
            }
            __syncthreads();

            // pair sweep: q>p overlaps in x iff x1_q < x2_p (x1 sorted ascending)
            for (int p = tid; p < V; p += TPB) {
                float4 fp = s_f4[p];                // (x2, y1, y2, area)
                float x2p = fp.x, y1p = fp.y, y2p = fp.z, arp = fp.w;
                int rp = srank[p];
                for (int q = p + 1; q < V; q++) {
                    float x1q = sx1[q];
                    if (x1q >= x2p) break;
                    float4 fq = s_f4[q];
                    float w_ = fminf(x2p, fq.x) - x1q;               // == ref (max(x1)=x1q)
                    float h_ = fminf(y2p, fq.z) - fmaxf(y1p, fq.y);
                    if (h_ > 0.0f) {
                        float inter = w_ * h_;
                        float uni = arp + fq.w - inter;
                        if (inter / fmaxf(uni, 1e-8f) > IOU_THR) {
                            int rq = srank[q];
                            int imin = rp < rq ? rp : rq;
                            int jmax = rp < rq ? rq : rp;
                            atomicOr(&s_mask[imin * WMAX + (jmax >> 5)], 1u << (jmax & 31));
                            s_any[imin] = 1;
                        }
                    }
                }
            }
            __syncthreads();

            // chunked serial greedy sweep (warp 0)
            if (tid < 32) {
                int W = (K_eff + 31) >> 5;
                unsigned sup = 0;
                int nk = 0;
                int nchunk = (K_eff + 31) >> 5;
                for (int g = 0; g < nchunk && nk < MAX_DET; g++) {
                    unsigned ow = __shfl_sync(0xffffffffu, sup, g);
                    int bend = min(32, K_eff - (g << 5));
                    for (int bb2 = 0; bb2 < bend; bb2++) {
                        if (!(ow & (1u << bb2))) {
                            int i = (g << 5) + bb2;
                            if (tid == 0) {
                                unsigned long long kk = s_key[i];
                                g_keep_score[bc * MAX_DET + nk] = __uint_as_float((unsigned)(kk >> 32));
                                g_keep_idx[bc * MAX_DET + nk]   = (int)(~((unsigned)kk));
                            }
                            unsigned m = (tid < W && s_any[i]) ? s_mask[i * WMAX + tid] : 0u;
                            sup |= m;
                            ow  |= __shfl_sync(0xffffffffu, m, g);
                            nk++;
                            if (nk >= MAX_DET) break;
                        }
                    }
                }
                if (tid == 0) g_keep_count[bc] = nk;
            }
        } else {
            // slow fallback: barrier greedy, boxes from global
            unsigned char* sup = (unsigned char*)s_mask;
            __shared__ int s_nk;
            for (int i = tid; i < K_eff; i += TPB) sup[i] = 0;
            if (tid == 0) s_nk = 0;
            __syncthreads();
            for (int i = 0; i < K_eff; i++) {
                if (!sup[i]) {
                    unsigned long long ki = s_key[i];
                    int ni = (int)(~((unsigned)ki));
                    if (tid == 0) {
                        int nk = s_nk;
                        g_keep_score[bc * MAX_DET + nk] = __uint_as_float((unsigned)(ki >> 32));
                        g_keep_idx[bc * MAX_DET + nk]   = ni;
                        s_nk = nk + 1;
                    }
                    float4 bi = reinterpret_cast<const float4*>(boxes)[b * N_BOX + ni];
                    float ai = (bi.z - bi.x) * (bi.w - bi.y);
                    for (int j = i + 1 + tid; j < K_eff; j += TPB) {
                        if (!sup[j]) {
                            int nj = (int)(~((unsigned)s_key[j]));
                            float4 bj = reinterpret_cast<const float4*>(boxes)[b * N_BOX + nj];
                            float aj = (bj.z - bj.x) * (bj.w - bj.y);
                            float w_ = fmaxf(fminf(bi.z, bj.z) - fmaxf(bi.x, bj.x), 0.0f);
                            float h_ = fmaxf(fminf(bi.w, bj.w) - fmaxf(bi.y, bj.y), 0.0f);
                            float inter = w_ * h_;
                            float uni = ai + aj - inter;
                            if (inter / fmaxf(uni, 1e-8f) > IOU_THR) sup[j] = 1;
                        }
                    }
                    __syncthreads();
                    if (s_nk >= MAX_DET) break;
                }
            }
            if (tid == 0) g_keep_count[bc] = (s_nk <= MAX_DET) ? s_nk : MAX_DET;
        }
    }

    // ===== finisher ticket: last B_IMG finishers run the merge =====
    __threadfence();
    __syncthreads();
    if (tid == 0) s_ticket = atomicAdd(&g_done, 1);
    __syncthreads();
    int ticket = s_ticket;
    if (ticket < GRID - B_IMG) return;
    const int img = ticket - (GRID - B_IMG);
    if (tid == 0) {
        while (*(volatile int*)&g_done < GRID) {}
        int r = atomicAdd(&g_done2, 1);
        if (r == B_IMG - 1) { g_done = 0; g_done2 = 0; g_b1 = 0; }   // reset for replay
    }
    __syncthreads();
    __threadfence();

    // ===== phase 3: per-image radix-select top-300 (truncated + exact fallback) =====
    {
        unsigned* s_u    = (unsigned*)dynbuf;                         // C_CLS*WIN
        int*      hist   = (int*)(s_u + C_CLS * WIN);                 // NB
        int*      scan   = hist + NB;                                 // TPB
        int*      s_ccnt = scan + TPB;                                // C_CLS
        unsigned long long* s_k3 = (unsigned long long*)(s_ccnt + C_CLS); // CCAP
        __shared__ int s_res[2];
        __shared__ int s_ncoll;
        __shared__ unsigned s_maxtr;

        if (tid < C_CLS) s_ccnt[tid] = g_keep_count[img * C_CLS + tid];
        if (tid == 0) { s_maxtr = 0; s_ncoll = 0; }
        __syncthreads();
        if (tid < C_CLS && s_ccnt[tid] > WIN)
            atomicMax(&s_maxtr, __float_as_uint(g_keep_score[(img * C_CLS + tid) * MAX_DET + WIN]));
        __syncthreads();

        unsigned Tu = 0;
        bool found = false;
        int win = WIN, pool = C_CLS * WIN, fmode = 0;

        for (int mode = 0; mode < 2; mode++) {
            win = mode ? MAX_DET : WIN;
            pool = C_CLS * win;
            fmode = mode;

            for (int i = tid; i < 1024; i += TPB) hist[i] = 0;
            __syncthreads();
            for (int t = tid; t < pool; t += TPB) {
                int cc = t / win, r = t % win;
                unsigned u = (r < s_ccnt[cc])
                           ? __float_as_uint(g_keep_score[(img * C_CLS + cc) * MAX_DET + r]) : 0;
                if (!mode) s_u[t] = u;
                if (u) atomicAdd(&hist[u >> 22], 1);
            }
            __syncthreads();
            find_cross(hist, 1024, MAX_DET, tid, scan, s_res);
            __syncthreads();
            int b1 = s_res[0], na1 = s_res[1];
            found = (b1 >= 0);
            Tu = 0;

            if (found) {
                for (int i = tid; i < NB; i += TPB) hist[i] = 0;
                __syncthreads();
                for (int t = tid; t < pool; t += TPB) {
                    unsigned u;
                    if (!mode) u = s_u[t];
                    else {
                        int cc = t / win, r = t % win;
                        u = (r < s_ccnt[cc])
                          ? __float_as_uint(g_keep_score[(img * C_CLS + cc) * MAX_DET + r]) : 0;
                    }
                    if (u && (int)(u >> 22) == b1) atomicAdd(&hist[(u >> 11) & 0x7FF], 1);
                }
                __syncthreads();
                find_cross(hist, 2048, MAX_DET - na1, tid, scan, s_res);
                __syncthreads();
                int b2 = s_res[0], na2 = s_res[1];
                unsigned p2 = ((unsigned)b1 << 11) | (unsigned)b2;

                for (int i = tid; i < NB; i += TPB) hist[i] = 0;
                __syncthreads();
                for (int t = tid; t < pool; t += TPB) {
                    unsigned u;
                    if (!mode) u = s_u[t];
                    else {
                        int cc = t / win, r = t % win;
                        u = (r < s_ccnt[cc])
                          ? __float_as_uint(g_keep_score[(img * C_CLS + cc) * MAX_DET + r]) : 0;
                    }
                    if (u && (u >> 11) == p2) atomicAdd(&hist[u & 0x7FF], 1);
                }
                __syncthreads();
                find_cross(hist, 2048, MAX_DET - na1 - na2, tid, scan, s_res);
                __syncthreads();
                Tu = (p2 << 11) | (unsigned)s_res[0];
            }
            __syncthreads();

            if (mode == 0) {
                bool valid = found ? (Tu > s_maxtr) : (s_maxtr == 0);
                if (valid) break;
            }
        }

        for (int t = tid; t < pool; t += TPB) {
            unsigned u;
            int cc = t / win, r = t % win;
            if (!fmode) u = s_u[t];
            else u = (r < s_ccnt[cc])
                   ? __float_as_uint(g_keep_score[(img * C_CLS + cc) * MAX_DET + r]) : 0;
            if (u && (!found || u >= Tu)) {
                int pos = atomicAdd(&s_ncoll, 1);
                if (pos < CCAP) {
                    int flat = cc * MAX_DET + r;
                    s_k3[pos] = ((unsigned long long)u << 16) | (unsigned)(0xFFFF - flat);
                }
            }
        }
        __syncthreads();
        int Ncoll = s_ncoll < CCAP ? s_ncoll : CCAP;
        int M2 = 1;
        while (M2 < Ncoll) M2 <<= 1;
        for (int i = tid; i < M2; i += TPB) if (i >= Ncoll) s_k3[i] = 0ull;
        __syncthreads();

        bitonic_desc(s_k3, M2, tid);

        if (tid < MAX_DET) {
            float* fb = out + img * (MAX_DET * 4) + tid * 4;
            float* fs = out + B_IMG * MAX_DET * 4 + img * MAX_DET + tid;
            float* fl = out + B_IMG * MAX_DET * 4 + B_IMG * MAX_DET + img * MAX_DET + tid;
            if (tid < Ncoll) {
                unsigned long long kk = s_k3[tid];
                unsigned u = (unsigned)(kk >> 16);
                int flat = 0xFFFF - (int)(kk & 0xFFFF);
                int cc = flat / MAX_DET, r = flat % MAX_DET;
                int n = g_keep_idx[(img * C_CLS + cc) * MAX_DET + r];
                float4 bb = reinterpret_cast<const float4*>(boxes)[img * N_BOX + n];
                fb[0] = bb.x; fb[1] = bb.y; fb[2] = bb.z; fb[3] = bb.w;
                *fs = __uint_as_float(u);
                *fl = (float)cc;
            } else {
                fb[0] = -1.0f; fb[1] = -1.0f; fb[2] = -1.0f; fb[3] = -1.0f;
                *fs = -1.0f; *fl = -1.0f;
            }
        }
    }
}

// ---------------- host launcher ----------------
extern "C" void kernel_launch(void* const* d_in, const int* in_sizes, int n_in,
                              void* d_out, int out_size) {
    const float* boxes = (const float*)d_in[0];           // [2,20000,4]
    const float* cls   = (const float*)d_in[1];           // [2,20000,80]
    const float* cen   = (const float*)d_in[2];           // [2,20000,1]
    float* out = (float*)d_out;                           // fb(2400) | fs(600) | fl(600)

    cudaFuncSetAttribute(fused_kernel,
                         cudaFuncAttributeMaxDynamicSharedMemorySize, SMEM_BYTES);

    fused_kernel<<<GRID, TPB, SMEM_BYTES>>>(boxes, (const float4*)cls, cen, out);
}

// round 8
// speedup vs baseline: 2.1185x; 1.0158x over previous
#include <cuda_runtime.h>
#include <float.h>

#define B_IMG 2
#define N_BOX 20000
#define C_CLS 80
#define BC (B_IMG * C_CLS)          // 160
#define CAP 1024                    // global candidate cap per (b,c)
#define CPAD 32                     // counter padding (128B stride)
#define MAXV 512                    // fast-path NMS limit; slow fallback beyond
#define WMAX (MAXV / 32)            // 16
#define PRE_K 1000
#define MAX_DET 300
#define SCORE_THR 0.05f
#define IOU_THR 0.5f
#define WIN 64
#define NB 2048
#define CCAP 2048
#define GRID 160
#define TPB 512
#define BATCH 10                    // ceil(800000 / 81920)
#define SMEM_BYTES 67584

// ---------------- scratch (no allocations allowed) ----------------
__device__ int   g_b1, g_done, g_done2;      // barrier + finisher tickets (start 0, self-reset)
__device__ int   g_cand_count[BC * CPAD];
__device__ float g_cand_score[BC * CAP];
__device__ int   g_cand_idx[BC * CAP];
__device__ int   g_keep_count[BC];
__device__ float g_keep_score[BC * MAX_DET];
__device__ int   g_keep_idx[BC * MAX_DET];

// ---- descending bitonic sort of M (pow2) 64-bit keys; hybrid shfl/smem ----
__device__ __forceinline__ void bitonic_desc(unsigned long long* sk, int M, int tid) {
    if (M <= 1) return;
    if (M <= TPB) {
        unsigned long long key = (tid < M) ? sk[tid] : 0ull;
        int kreg = M < 32 ? M : 32;
        for (int k = 2; k <= kreg; k <<= 1) {
            bool up_k = ((tid & k) == 0);
            for (int j = k >> 1; j > 0; j >>= 1) {
                unsigned long long oth = __shfl_xor_sync(0xffffffffu, key, j);
                bool lower = ((tid & j) == 0);
                bool take_max = (up_k == lower);
                key = take_max ? (key > oth ? key : oth) : (key < oth ? key : oth);
            }
        }
        for (int k = 64; k <= M; k <<= 1) {
            if (tid < M) sk[tid] = key;
            __syncthreads();
            for (int j = k >> 1; j >= 32; j >>= 1) {
                int ixj = tid ^ j;
                if (tid < M && ixj > tid) {
                    unsigned long long a = sk[tid], d = sk[ixj];
                    bool up = ((tid & k) == 0);
                    if (up ? (a < d) : (a > d)) { sk[tid] = d; sk[ixj] = a; }
                }
                __syncthreads();
            }
            key = (tid < M) ? sk[tid] : 0ull;
            bool up_k = ((tid & k) == 0);
            for (int j = 16; j > 0; j >>= 1) {
                unsigned long long oth = __shfl_xor_sync(0xffffffffu, key, j);
                bool lower = ((tid & j) == 0);
                bool take_max = (up_k == lower);
                key = take_max ? (key > oth ? key : oth) : (key < oth ? key : oth);
            }
        }
        if (tid < M) sk[tid] = key;
        __syncthreads();
    } else {
        for (int k = 2; k <= M; k <<= 1) {
            for (int j = k >> 1; j > 0; j >>= 1) {
                for (int i = tid; i < M; i += TPB) {
                    int ixj = i ^ j;
                    if (ixj > i) {
                        unsigned long long a = sk[i], d = sk[ixj];
                        bool up = ((i & k) == 0);
                        if (up ? (a < d) : (a > d)) { sk[i] = d; sk[ixj] = a; }
                    }
                }
                __syncthreads();
            }
        }
    }
}

// ---- block-parallel suffix-scan bucket finder ----
__device__ __forceinline__ void find_cross(const int* hist, int nb, int rem,
                                           int tid, int* scan, int* res) {
    int chunk = nb / TPB;
    int base = tid * chunk;
    int lsum = 0;
    for (int k = 0; k < chunk; k++) lsum += hist[base + k];
    scan[tid] = lsum;
    __syncthreads();
    for (int off = 1; off < TPB; off <<= 1) {
        int v = (tid + off < TPB) ? scan[tid + off] : 0;
        __syncthreads();
        scan[tid] += v;
        __syncthreads();
    }
    int incl = scan[tid];
    int total = scan[0];
    if (tid == 0 && total < rem) { res[0] = -1; res[1] = total; }
    if (total >= rem) {
        int after = incl - lsum;
        if (after < rem && rem <= incl) {
            int cum = after;
            for (int k = chunk - 1; k >= 0; k--) {
                int h = hist[base + k];
                cum += h;
                if (cum >= rem) { res[0] = base + k; res[1] = cum - h; break; }
            }
        }
    }
}

__global__ __launch_bounds__(TPB)
void fused_kernel(const float* __restrict__ boxes,
                  const float4* __restrict__ cls4,
                  const float* __restrict__ cen,
                  float* __restrict__ out) {
    extern __shared__ unsigned char dynbuf[];
    // phase-2 layout
    unsigned long long* s_key  = (unsigned long long*)dynbuf;            // CAP (8KB)
    float4*             s_box  = (float4*)(dynbuf + 8192);               // MAXV (8KB)
    unsigned long long* s_xkey = (unsigned long long*)(dynbuf + 16384);  // MAXV (4KB)
    float*              sx1    = (float*)(dynbuf + 20480);               // MAXV (2KB)
    float4*             s_f4   = (float4*)(dynbuf + 22528);              // MAXV (8KB)
    int*                srank  = (int*)(dynbuf + 30720);                 // MAXV (2KB)
    unsigned*           s_mask = (unsigned*)(dynbuf + 32768);            // MAXV*WMAX (32KB)
    int*                s_any  = (int*)(dynbuf + 65536);                 // MAXV (2KB)
    __shared__ int s_ticket;

    const int tid = threadIdx.x;
    const int bc  = blockIdx.x;
    const int b   = bc / C_CLS;

    // ===== phase 1: coalesced threshold + compact (batched loads, MLP=BATCH) =====
    {
        const int total4 = B_IMG * N_BOX * C_CLS / 4;     // 800000
        const int start  = bc * TPB + tid;
        const int stride = GRID * TPB;                    // 81920

        float4 vbuf[BATCH];
        float  cbuf[BATCH];
        #pragma unroll
        for (int k = 0; k < BATCH; k++) {
            int q = start + k * stride;
            if (q < total4) {
                vbuf[k] = cls4[q];
                cbuf[k] = cen[q / 20];    // q/20 == (b*N_BOX+n); exact since 80%4==0
            }
        }
        #pragma unroll
        for (int k = 0; k < BATCH; k++) {
            int q = start + k * stride;
            if (q < total4) {
                float4 v = vbuf[k];
                if (v.x > SCORE_THR || v.y > SCORE_THR || v.z > SCORE_THR || v.w > SCORE_THR) {
                    int base = q * 4;
                    int c0  = base % C_CLS;
                    int rem = q / 20;                 // b*N_BOX + n
                    int bb  = rem / N_BOX;
                    float ce = cbuf[k];
                    float vv[4] = {v.x, v.y, v.z, v.w};
                    #pragma unroll
                    for (int e = 0; e < 4; e++) {
                        if (vv[e] > SCORE_THR) {
                            float s = sqrtf(vv[e] * ce);
                            int idx = bb * C_CLS + c0 + e;
                            int pos = atomicAdd(&g_cand_count[idx * CPAD], 1);
                            if (pos < CAP) {
                                g_cand_score[idx * CAP + pos] = s;
                                g_cand_idx[idx * CAP + pos]   = rem % N_BOX;
                            }
                        }
                    }
                }
            }
        }
    }

    // ---- grid barrier 1 ----
    __threadfence();
    __syncthreads();
    if (tid == 0) {
        atomicAdd(&g_b1, 1);
        while (*(volatile int*)&g_b1 < GRID) {}
    }
    __syncthreads();
    __threadfence();

    // ===== phase 2: score sort + x-sweep NMS =====
    int V = g_cand_count[bc * CPAD];
    if (V > CAP) V = CAP;
    {
        int M = 1;
        while (M < V) M <<= 1;

        for (int i = tid; i < M; i += TPB) {
            if (i < V) {
                unsigned sb = __float_as_uint(g_cand_score[bc * CAP + i]);
                unsigned ix = (unsigned)g_cand_idx[bc * CAP + i];
                s_key[i] = ((unsigned long long)sb << 32) | (unsigned)(~ix);
            } else {
                s_key[i] = 0ull;
            }
        }
        __syncthreads();
        if (tid == 0) g_cand_count[bc * CPAD] = 0;   // re-zero for next replay

        bitonic_desc(s_key, M, tid);                 // score desc, tie -> smaller idx

        int K_eff = V < PRE_K ? V : PRE_K;

        if (V <= MAXV) {
            for (int i = tid; i < V; i += TPB) {
                int n = (int)(~((unsigned)s_key[i]));
                s_box[i] = reinterpret_cast<const float4*>(boxes)[b * N_BOX + n];
            }
            for (int t = tid; t < V * WMAX; t += TPB) s_mask[t] = 0u;
            for (int i = tid; i < V; i += TPB) s_any[i] = 0;
            __syncthreads();

            int Mx = M <= MAXV ? M : MAXV;
            for (int i = tid; i < Mx; i += TPB) {
                s_xkey[i] = (i < V)
                    ? ((unsigned long long)(~__float_as_uint(s_box[i].x)) << 32) | (unsigned)i
                    : 0ull;
            }
            __syncthreads();
            bitonic_desc(s_xkey, Mx, tid);

            for (int p = tid; p < V; p += TPB) {
                int r = (int)(unsigned)s_xkey[p];
                float4 bb4 = s_box[r];
                sx1[p] = bb4.x;
                s_f4[p] = make_float4(bb4.z, bb4.y, bb4.w,
                                      (bb4.z - bb4.x) * (bb4.w - bb4.y));
                srank[p] = r;
            }
            __syncthreads();

            // pair sweep: q>p overlaps in x iff x1_q < x2_p (x1 sorted ascending)
            for (int p = tid; p < V; p += TPB) {
                float4 fp = s_f4[p];                // (x2, y1, y2, area)
                float x2p = fp.x, y1p = fp.y, y2p = fp.z, arp = fp.w;
                int rp = srank[p];
                for (int q = p + 1; q < V; q++) {
                    float x1q = sx1[q];
                    if (x1q >= x2p) break;
                    float4 fq = s_f4[q];
                    float w_ = fminf(x2p, fq.x) - x1q;
                    float h_ = fminf(y2p, fq.z) - fmaxf(y1p, fq.y);
                    if (h_ > 0.0f) {
                        float inter = w_ * h_;
                        float uni = arp + fq.w - inter;
                        if (inter / fmaxf(uni, 1e-8f) > IOU_THR) {
                            int rq = srank[q];
                            int imin = rp < rq ? rp : rq;
                            int jmax = rp < rq ? rq : rp;
                            atomicOr(&s_mask[imin * WMAX + (jmax >> 5)], 1u << (jmax & 31));
                            s_any[imin] = 1;
                        }
                    }
                }
            }
            __syncthreads();

            if (tid < 32) {
                int W = (K_eff + 31) >> 5;
                unsigned sup = 0;
                int nk = 0;
                int nchunk = (K_eff + 31) >> 5;
                for (int g = 0; g < nchunk && nk < MAX_DET; g++) {
                    unsigned ow = __shfl_sync(0xffffffffu, sup, g);
                    int bend = min(32, K_eff - (g << 5));
                    for (int bb2 = 0; bb2 < bend; bb2++) {
                        if (!(ow & (1u << bb2))) {
                            int i = (g << 5) + bb2;
                            if (tid == 0) {
                                unsigned long long kk = s_key[i];
                                g_keep_score[bc * MAX_DET + nk] = __uint_as_float((unsigned)(kk >> 32));
                                g_keep_idx[bc * MAX_DET + nk]   = (int)(~((unsigned)kk));
                            }
                            unsigned m = (tid < W && s_any[i]) ? s_mask[i * WMAX + tid] : 0u;
                            sup |= m;
                            ow  |= __shfl_sync(0xffffffffu, m, g);
                            nk++;
                            if (nk >= MAX_DET) break;
                        }
                    }
                }
                if (tid == 0) g_keep_count[bc] = nk;
            }
        } else {
            // slow fallback: barrier greedy, boxes from global
            unsigned char* sup = (unsigned char*)s_mask;
            __shared__ int s_nk;
            for (int i = tid; i < K_eff; i += TPB) sup[i] = 0;
            if (tid == 0) s_nk = 0;
            __syncthreads();
            for (int i = 0; i < K_eff; i++) {
                if (!sup[i]) {
                    unsigned long long ki = s_key[i];
                    int ni = (int)(~((unsigned)ki));
                    if (tid == 0) {
                        int nk = s_nk;
                        g_keep_score[bc * MAX_DET + nk] = __uint_as_float((unsigned)(ki >> 32));
                        g_keep_idx[bc * MAX_DET + nk]   = ni;
                        s_nk = nk + 1;
                    }
                    float4 bi = reinterpret_cast<const float4*>(boxes)[b * N_BOX + ni];
                    float ai = (bi.z - bi.x) * (bi.w - bi.y);
                    for (int j = i + 1 + tid; j < K_eff; j += TPB) {
                        if (!sup[j]) {
                            int nj = (int)(~((unsigned)s_key[j]));
                            float4 bj = reinterpret_cast<const float4*>(boxes)[b * N_BOX + nj];
                            float aj = (bj.z - bj.x) * (bj.w - bj.y);
                            float w_ = fmaxf(fminf(bi.z, bj.z) - fmaxf(bi.x, bj.x), 0.0f);
                            float h_ = fmaxf(fminf(bi.w, bj.w) - fmaxf(bi.y, bj.y), 0.0f);
                            float inter = w_ * h_;
                            float uni = ai + aj - inter;
                            if (inter / fmaxf(uni, 1e-8f) > IOU_THR) sup[j] = 1;
                        }
                    }
                    __syncthreads();
                    if (s_nk >= MAX_DET) break;
                }
            }
            if (tid == 0) g_keep_count[bc] = (s_nk <= MAX_DET) ? s_nk : MAX_DET;
        }
    }

    // ===== finisher ticket: last B_IMG finishers run the merge =====
    __threadfence();
    __syncthreads();
    if (tid == 0) s_ticket = atomicAdd(&g_done, 1);
    __syncthreads();
    int ticket = s_ticket;
    if (ticket < GRID - B_IMG) return;
    const int img = ticket - (GRID - B_IMG);
    if (tid == 0) {
        while (*(volatile int*)&g_done < GRID) {}
        int r = atomicAdd(&g_done2, 1);
        if (r == B_IMG - 1) { g_done = 0; g_done2 = 0; g_b1 = 0; }   // reset for replay
    }
    __syncthreads();
    __threadfence();

    // ===== phase 3: per-image radix-select top-300 (truncated + exact fallback) =====
    {
        unsigned* s_u    = (unsigned*)dynbuf;                         // C_CLS*WIN
        int*      hist   = (int*)(s_u + C_CLS * WIN);                 // NB
        int*      scan   = hist + NB;                                 // TPB
        int*      s_ccnt = scan + TPB;                                // C_CLS
        unsigned long long* s_k3 = (unsigned long long*)(s_ccnt + C_CLS); // CCAP
        __shared__ int s_res[2];
        __shared__ int s_ncoll;
        __shared__ unsigned s_maxtr;

        if (tid < C_CLS) s_ccnt[tid] = g_keep_count[img * C_CLS + tid];
        if (tid == 0) { s_maxtr = 0; s_ncoll = 0; }
        __syncthreads();
        if (tid < C_CLS && s_ccnt[tid] > WIN)
            atomicMax(&s_maxtr, __float_as_uint(g_keep_score[(img * C_CLS + tid) * MAX_DET + WIN]));
        __syncthreads();

        unsigned Tu = 0;
        bool found = false;
        int win = WIN, pool = C_CLS * WIN, fmode = 0;

        for (int mode = 0; mode < 2; mode++) {
            win = mode ? MAX_DET : WIN;
            pool = C_CLS * win;
            fmode = mode;

            for (int i = tid; i < 1024; i += TPB) hist[i] = 0;
            __syncthreads();
            for (int t = tid; t < pool; t += TPB) {
                int cc = t / win, r = t % win;
                unsigned u = (r < s_ccnt[cc])
                           ? __float_as_uint(g_keep_score[(img * C_CLS + cc) * MAX_DET + r]) : 0;
                if (!mode) s_u[t] = u;
                if (u) atomicAdd(&hist[u >> 22], 1);
            }
            __syncthreads();
            find_cross(hist, 1024, MAX_DET, tid, scan, s_res);
            __syncthreads();
            int b1 = s_res[0], na1 = s_res[1];
            found = (b1 >= 0);
            Tu = 0;

            if (found) {
                for (int i = tid; i < NB; i += TPB) hist[i] = 0;
                __syncthreads();
                for (int t = tid; t < pool; t += TPB) {
                    unsigned u;
                    if (!mode) u = s_u[t];
                    else {
                        int cc = t / win, r = t % win;
                        u = (r < s_ccnt[cc])
                          ? __float_as_uint(g_keep_score[(img * C_CLS + cc) * MAX_DET + r]) : 0;
                    }
                    if (u && (int)(u >> 22) == b1) atomicAdd(&hist[(u >> 11) & 0x7FF], 1);
                }
                __syncthreads();
                find_cross(hist, 2048, MAX_DET - na1, tid, scan, s_res);
                __syncthreads();
                int b2 = s_res[0], na2 = s_res[1];
                unsigned p2 = ((unsigned)b1 << 11) | (unsigned)b2;

                for (int i = tid; i < NB; i += TPB) hist[i] = 0;
                __syncthreads();
                for (int t = tid; t < pool; t += TPB) {
                    unsigned u;
                    if (!mode) u = s_u[t];
                    else {
                        int cc = t / win, r = t % win;
                        u = (r < s_ccnt[cc])
                          ? __float_as_uint(g_keep_score[(img * C_CLS + cc) * MAX_DET + r]) : 0;
                    }
                    if (u && (u >> 11) == p2) atomicAdd(&hist[u & 0x7FF], 1);
                }
                __syncthreads();
                find_cross(hist, 2048, MAX_DET - na1 - na2, tid, scan, s_res);
                __syncthreads();
                Tu = (p2 << 11) | (unsigned)s_res[0];
            }
            __syncthreads();

            if (mode == 0) {
                bool valid = found ? (Tu > s_maxtr) : (s_maxtr == 0);
                if (valid) break;
            }
        }

        for (int t = tid; t < pool; t += TPB) {
            unsigned u;
            int cc = t / win, r = t % win;
            if (!fmode) u = s_u[t];
            else u = (r < s_ccnt[cc])
                   ? __float_as_uint(g_keep_score[(img * C_CLS + cc) * MAX_DET + r]) : 0;
            if (u && (!found || u >= Tu)) {
                int pos = atomicAdd(&s_ncoll, 1);
                if (pos < CCAP) {
                    int flat = cc * MAX_DET + r;
                    s_k3[pos] = ((unsigned long long)u << 16) | (unsigned)(0xFFFF - flat);
                }
            }
        }
        __syncthreads();
        int Ncoll = s_ncoll < CCAP ? s_ncoll : CCAP;
        int M2 = 1;
        while (M2 < Ncoll) M2 <<= 1;
        for (int i = tid; i < M2; i += TPB) if (i >= Ncoll) s_k3[i] = 0ull;
        __syncthreads();

        bitonic_desc(s_k3, M2, tid);

        if (tid < MAX_DET) {
            float* fb = out + img * (MAX_DET * 4) + tid * 4;
            float* fs = out + B_IMG * MAX_DET * 4 + img * MAX_DET + tid;
            float* fl = out + B_IMG * MAX_DET * 4 + B_IMG * MAX_DET + img * MAX_DET + tid;
            if (tid < Ncoll) {
                unsigned long long kk = s_k3[tid];
                unsigned u = (unsigned)(kk >> 16);
                int flat = 0xFFFF - (int)(kk & 0xFFFF);
                int cc = flat / MAX_DET, r = flat % MAX_DET;
                int n = g_keep_idx[(img * C_CLS + cc) * MAX_DET + r];
                float4 bb = reinterpret_cast<const float4*>(boxes)[img * N_BOX + n];
                fb[0] = bb.x; fb[1] = bb.y; fb[2] = bb.z; fb[3] = bb.w;
                *fs = __uint_as_float(u);
                *fl = (float)cc;
            } else {
                fb[0] = -1.0f; fb[1] = -1.0f; fb[2] = -1.0f; fb[3] = -1.0f;
                *fs = -1.0f; *fl = -1.0f;
            }
        }
    }
}

// ---------------- host launcher ----------------
extern "C" void kernel_launch(void* const* d_in, const int* in_sizes, int n_in,
                              void* d_out, int out_size) {
    const float* boxes = (const float*)d_in[0];           // [2,20000,4]
    const float* cls   = (const float*)d_in[1];           // [2,20000,80]
    const float* cen   = (const float*)d_in[2];           // [2,20000,1]
    float* out = (float*)d_out;                           // fb(2400) | fs(600) | fl(600)

    cudaFuncSetAttribute(fused_kernel,
                         cudaFuncAttributeMaxDynamicSharedMemorySize, SMEM_BYTES);

    fused_kernel<<<GRID, TPB, SMEM_BYTES>>>(boxes, (const float4*)cls, cen, out);
}

// round 9
// speedup vs baseline: 2.1613x; 1.0202x over previous
#include <cuda_runtime.h>
#include <float.h>

#define B_IMG 2
#define N_BOX 20000
#define C_CLS 80
#define BC (B_IMG * C_CLS)          // 160
#define CAP 1024                    // global candidate cap per (b,c)
#define CPAD 32                     // counter padding (128B stride)
#define MAXV 512                    // fast-path NMS limit; slow fallback beyond
#define WMAX (MAXV / 32)            // 16
#define PRE_K 1000
#define MAX_DET 300
#define SCORE_THR 0.05f
#define IOU_THR 0.5f
#define WIN 64
#define NB 2048
#define CCAP 2048
#define GRID 160
#define TPB 512
#define NWARP (TPB / 32)
#define BATCH 10
#define SMEM_BYTES 67584

// ---------------- scratch (no allocations allowed) ----------------
__device__ int   g_b1, g_done, g_done2;      // barrier + finisher tickets (start 0, self-reset)
__device__ int   g_cand_count[BC * CPAD];
__device__ float g_cand_score[BC * CAP];
__device__ int   g_cand_idx[BC * CAP];
__device__ int   g_keep_count[BC];
__device__ float g_keep_score[BC * MAX_DET];
__device__ int   g_keep_idx[BC * MAX_DET];

// ---- smem bitonic (slow fallback only, M > TPB) ----
__device__ __forceinline__ void bitonic_desc(unsigned long long* sk, int M, int tid) {
    for (int k = 2; k <= M; k <<= 1) {
        for (int j = k >> 1; j > 0; j >>= 1) {
            for (int i = tid; i < M; i += TPB) {
                int ixj = i ^ j;
                if (ixj > i) {
                    unsigned long long a = sk[i], d = sk[ixj];
                    bool up = ((i & k) == 0);
                    if (up ? (a < d) : (a > d)) { sk[i] = d; sk[ixj] = a; }
                }
            }
            __syncthreads();
        }
    }
}

// ---- 2-barrier bucket finder: warp suffix-scan + broadcast warp totals ----
// res[0] = bucket containing element #rem counting from top (-1 if total<rem)
// res[1] = count strictly above that bucket
__device__ __forceinline__ void find_cross(const int* hist, int nb, int rem,
                                           int tid, int* warp_tot, int* res) {
    int chunk = nb / TPB;
    int base = tid * chunk;
    int lsum = 0;
    for (int k = 0; k < chunk; k++) lsum += hist[base + k];

    int lane = tid & 31, wid = tid >> 5;
    int suff = lsum;                           // warp-level suffix sum (desc index order)
    #pragma unroll
    for (int off = 1; off < 32; off <<= 1) {
        int v = __shfl_down_sync(0xffffffffu, suff, off);
        if (lane + off < 32) suff += v;
    }
    if (lane == 0) warp_tot[wid] = suff;       // warp total (= lane 0's suffix)
    __syncthreads();

    int after_w = 0, total = 0;
    #pragma unroll
    for (int w = 0; w < NWARP; w++) {
        int wt = warp_tot[w];                  // broadcast read
        total += wt;
        if (w > wid) after_w += wt;
    }
    int incl = after_w + suff;                 // entries in buckets >= my chunk base
    int after_c = incl - lsum;                 // entries in buckets >= chunk end
    if (tid == 0 && total < rem) { res[0] = -1; res[1] = total; }
    if (total >= rem && after_c < rem && rem <= incl) {
        int cum = after_c;
        for (int k = chunk - 1; k >= 0; k--) {
            int h = hist[base + k];
            cum += h;
            if (cum >= rem) { res[0] = base + k; res[1] = cum - h; break; }
        }
    }
}

__global__ __launch_bounds__(TPB)
void fused_kernel(const float* __restrict__ boxes,
                  const float4* __restrict__ cls4,
                  const float* __restrict__ cen,
                  float* __restrict__ out) {
    extern __shared__ unsigned char dynbuf[];
    // phase-2 layout
    unsigned long long* s_key  = (unsigned long long*)dynbuf;            // CAP (8KB)
    float4*             s_box  = (float4*)(dynbuf + 8192);               // MAXV (8KB)
    unsigned long long* s_xkey = (unsigned long long*)(dynbuf + 16384);  // MAXV (4KB)
    float*              sx1    = (float*)(dynbuf + 20480);               // MAXV (2KB)
    float4*             s_f4   = (float4*)(dynbuf + 22528);              // MAXV (8KB)
    int*                srank  = (int*)(dynbuf + 30720);                 // MAXV (2KB)
    unsigned*           s_mask = (unsigned*)(dynbuf + 32768);            // MAXV*WMAX (32KB)
    int*                s_any  = (int*)(dynbuf + 65536);                 // MAXV (2KB)
    __shared__ int s_ticket;

    const int tid = threadIdx.x;
    const int bc  = blockIdx.x;
    const int b   = bc / C_CLS;

    // ===== phase 1: coalesced threshold + compact (batched loads) =====
    {
        const int total4 = B_IMG * N_BOX * C_CLS / 4;     // 800000
        const int start  = bc * TPB + tid;
        const int stride = GRID * TPB;                    // 81920

        float4 vbuf[BATCH];
        float  cbuf[BATCH];
        #pragma unroll
        for (int k = 0; k < BATCH; k++) {
            int q = start + k * stride;
            if (q < total4) {
                vbuf[k] = cls4[q];
                cbuf[k] = cen[q / 20];    // q/20 == b*N_BOX+n (80%4==0)
            }
        }
        #pragma unroll
        for (int k = 0; k < BATCH; k++) {
            int q = start + k * stride;
            if (q < total4) {
                float4 v = vbuf[k];
                if (v.x > SCORE_THR || v.y > SCORE_THR || v.z > SCORE_THR || v.w > SCORE_THR) {
                    int base = q * 4;
                    int c0  = base % C_CLS;
                    int rem = q / 20;
                    int bb  = rem / N_BOX;
                    float ce = cbuf[k];
                    float vv[4] = {v.x, v.y, v.z, v.w};
                    #pragma unroll
                    for (int e = 0; e < 4; e++) {
                        if (vv[e] > SCORE_THR) {
                            float s = sqrtf(vv[e] * ce);
                            int idx = bb * C_CLS + c0 + e;
                            int pos = atomicAdd(&g_cand_count[idx * CPAD], 1);
                            if (pos < CAP) {
                                g_cand_score[idx * CAP + pos] = s;
                                g_cand_idx[idx * CAP + pos]   = rem % N_BOX;
                            }
                        }
                    }
                }
            }
        }
    }

    // ---- grid barrier 1 ----
    __threadfence();
    __syncthreads();
    if (tid == 0) {
        atomicAdd(&g_b1, 1);
        while (*(volatile int*)&g_b1 < GRID) {}
    }
    __syncthreads();
    __threadfence();

    // ===== phase 2: score rank-sort + x-sweep NMS =====
    int V = g_cand_count[bc * CPAD];
    if (V > CAP) V = CAP;
    {
        int M = 1;
        while (M < V) M <<= 1;

        for (int i = tid; i < M; i += TPB) {
            if (i < V) {
                unsigned sb = __float_as_uint(g_cand_score[bc * CAP + i]);
                unsigned ix = (unsigned)g_cand_idx[bc * CAP + i];
                s_key[i] = ((unsigned long long)sb << 32) | (unsigned)(~ix);
            } else {
                s_key[i] = 0ull;
            }
        }
        __syncthreads();
        if (tid == 0) g_cand_count[bc * CPAD] = 0;   // re-zero for next replay

        int K_eff = V < PRE_K ? V : PRE_K;

        if (V <= MAXV) {
            // ---- rank-sort by score key (unique keys), in-place scatter ----
            unsigned long long mykey = (tid < V) ? s_key[tid] : 0ull;
            int rank = 0;
            for (int j = 0; j < V; j++) rank += (s_key[j] > mykey);
            __syncthreads();
            if (tid < V) s_key[rank] = mykey;
            __syncthreads();

            // gather boxes in score order; zero masks
            for (int i = tid; i < V; i += TPB) {
                int n = (int)(~((unsigned)s_key[i]));
                s_box[i] = reinterpret_cast<const float4*>(boxes)[b * N_BOX + n];
            }
            for (int t = tid; t < V * WMAX; t += TPB) s_mask[t] = 0u;
            for (int i = tid; i < V; i += TPB) s_any[i] = 0;
            __syncthreads();

            // ---- rank-sort by x1 ascending (key = ~x1bits<<32 | scorerank) ----
            unsigned long long xkey = (tid < V)
                ? ((unsigned long long)(~__float_as_uint(s_box[tid].x)) << 32) | (unsigned)tid
                : 0ull;
            if (tid < V) s_xkey[tid] = xkey;
            __syncthreads();
            int xrank = 0;
            for (int j = 0; j < V; j++) xrank += (s_xkey[j] > xkey);
            __syncthreads();
            if (tid < V) s_xkey[xrank] = xkey;
            __syncthreads();

            // build x-order SoA
            for (int p = tid; p < V; p += TPB) {
                int r = (int)(unsigned)s_xkey[p];
                float4 bb4 = s_box[r];
                sx1[p] = bb4.x;
                s_f4[p] = make_float4(bb4.z, bb4.y, bb4.w,
                                      (bb4.z - bb4.x) * (bb4.w - bb4.y));
                srank[p] = r;
            }
            __syncthreads();

            // pair sweep: q>p overlaps in x iff x1_q < x2_p (x1 ascending)
            for (int p = tid; p < V; p += TPB) {
                float4 fp = s_f4[p];                // (x2, y1, y2, area)
                float x2p = fp.x, y1p = fp.y, y2p = fp.z, arp = fp.w;
                int rp = srank[p];
                for (int q = p + 1; q < V; q++) {
                    float x1q = sx1[q];
                    if (x1q >= x2p) break;
                    float4 fq = s_f4[q];
                    float w_ = fminf(x2p, fq.x) - x1q;
                    float h_ = fminf(y2p, fq.z) - fmaxf(y1p, fq.y);
                    if (h_ > 0.0f) {
                        float inter = w_ * h_;
                        float uni = arp + fq.w - inter;
                        if (inter / fmaxf(uni, 1e-8f) > IOU_THR) {
                            int rq = srank[q];
                            int imin = rp < rq ? rp : rq;
                            int jmax = rp < rq ? rq : rp;
                            atomicOr(&s_mask[imin * WMAX + (jmax >> 5)], 1u << (jmax & 31));
                            s_any[imin] = 1;
                        }
                    }
                }
            }
            __syncthreads();

            // chunked serial greedy sweep (warp 0)
            if (tid < 32) {
                int W = (K_eff + 31) >> 5;
                unsigned sup = 0;
                int nk = 0;
                int nchunk = (K_eff + 31) >> 5;
                for (int g = 0; g < nchunk && nk < MAX_DET; g++) {
                    unsigned ow = __shfl_sync(0xffffffffu, sup, g);
                    int bend = min(32, K_eff - (g << 5));
                    for (int bb2 = 0; bb2 < bend; bb2++) {
                        if (!(ow & (1u << bb2))) {
                            int i = (g << 5) + bb2;
                            if (tid == 0) {
                                unsigned long long kk = s_key[i];
                                g_keep_score[bc * MAX_DET + nk] = __uint_as_float((unsigned)(kk >> 32));
                                g_keep_idx[bc * MAX_DET + nk]   = (int)(~((unsigned)kk));
                            }
                            unsigned m = (tid < W && s_any[i]) ? s_mask[i * WMAX + tid] : 0u;
                            sup |= m;
                            ow  |= __shfl_sync(0xffffffffu, m, g);
                            nk++;
                            if (nk >= MAX_DET) break;
                        }
                    }
                }
                if (tid == 0) g_keep_count[bc] = nk;
            }
        } else {
            // slow fallback: full bitonic + barrier greedy, boxes from global
            bitonic_desc(s_key, M, tid);
            unsigned char* sup = (unsigned char*)s_mask;
            __shared__ int s_nk;
            for (int i = tid; i < K_eff; i += TPB) sup[i] = 0;
            if (tid == 0) s_nk = 0;
            __syncthreads();
            for (int i = 0; i < K_eff; i++) {
                if (!sup[i]) {
                    unsigned long long ki = s_key[i];
                    int ni = (int)(~((unsigned)ki));
                    if (tid == 0) {
                        int nk = s_nk;
                        g_keep_score[bc * MAX_DET + nk] = __uint_as_float((unsigned)(ki >> 32));
                        g_keep_idx[bc * MAX_DET + nk]   = ni;
                        s_nk = nk + 1;
                    }
                    float4 bi = reinterpret_cast<const float4*>(boxes)[b * N_BOX + ni];
                    float ai = (bi.z - bi.x) * (bi.w - bi.y);
                    for (int j = i + 1 + tid; j < K_eff; j += TPB) {
                        if (!sup[j]) {
                            int nj = (int)(~((unsigned)s_key[j]));
                            float4 bj = reinterpret_cast<const float4*>(boxes)[b * N_BOX + nj];
                            float aj = (bj.z - bj.x) * (bj.w - bj.y);
                            float w_ = fmaxf(fminf(bi.z, bj.z) - fmaxf(bi.x, bj.x), 0.0f);
                            float h_ = fmaxf(fminf(bi.w, bj.w) - fmaxf(bi.y, bj.y), 0.0f);
                            float inter = w_ * h_;
                            float uni = ai + aj - inter;
                            if (inter / fmaxf(uni, 1e-8f) > IOU_THR) sup[j] = 1;
                        }
                    }
                    __syncthreads();
                    if (s_nk >= MAX_DET) break;
                }
            }
            if (tid == 0) g_keep_count[bc] = (s_nk <= MAX_DET) ? s_nk : MAX_DET;
        }
    }

    // ===== finisher ticket: last B_IMG finishers run the merge =====
    __threadfence();
    __syncthreads();
    if (tid == 0) s_ticket = atomicAdd(&g_done, 1);
    __syncthreads();
    int ticket = s_ticket;
    if (ticket < GRID - B_IMG) return;
    const int img = ticket - (GRID - B_IMG);
    if (tid == 0) {
        while (*(volatile int*)&g_done < GRID) {}
        int r = atomicAdd(&g_done2, 1);
        if (r == B_IMG - 1) { g_done = 0; g_done2 = 0; g_b1 = 0; }   // reset for replay
    }
    __syncthreads();
    __threadfence();

    // ===== phase 3: per-image radix-select top-300 (truncated + exact fallback) =====
    {
        unsigned* s_u    = (unsigned*)dynbuf;                         // C_CLS*WIN (20KB)
        int*      hist   = (int*)(s_u + C_CLS * WIN);                 // NB (8KB)
        int*      wtot   = hist + NB;                                 // TPB (2KB; only 16 used)
        int*      s_ccnt = wtot + TPB;                                // C_CLS
        unsigned long long* s_k3 = (unsigned long long*)(s_ccnt + C_CLS); // CCAP (16KB)
        unsigned long long* s_sorted = s_k3 + CCAP;                   // MAX_DET (2.4KB)
        __shared__ int s_res[2];
        __shared__ int s_ncoll;
        __shared__ unsigned s_maxtr;

        if (tid < C_CLS) s_ccnt[tid] = g_keep_count[img * C_CLS + tid];
        if (tid == 0) { s_maxtr = 0; s_ncoll = 0; }
        __syncthreads();
        if (tid < C_CLS && s_ccnt[tid] > WIN)
            atomicMax(&s_maxtr, __float_as_uint(g_keep_score[(img * C_CLS + tid) * MAX_DET + WIN]));
        __syncthreads();

        unsigned Tu = 0;
        bool found = false;
        int win = WIN, pool = C_CLS * WIN, fmode = 0;

        for (int mode = 0; mode < 2; mode++) {
            win = mode ? MAX_DET : WIN;
            pool = C_CLS * win;
            fmode = mode;

            for (int i = tid; i < 1024; i += TPB) hist[i] = 0;
            __syncthreads();
            for (int t = tid; t < pool; t += TPB) {
                int cc = t / win, r = t % win;
                unsigned u = (r < s_ccnt[cc])
                           ? __float_as_uint(g_keep_score[(img * C_CLS + cc) * MAX_DET + r]) : 0;
                if (!mode) s_u[t] = u;
                if (u) atomicAdd(&hist[u >> 22], 1);
            }
            __syncthreads();
            find_cross(hist, 1024, MAX_DET, tid, wtot, s_res);
            __syncthreads();
            int b1 = s_res[0], na1 = s_res[1];
            found = (b1 >= 0);
            Tu = 0;

            if (found) {
                for (int i = tid; i < NB; i += TPB) hist[i] = 0;
                __syncthreads();
                for (int t = tid; t < pool; t += TPB) {
                    unsigned u;
                    if (!mode) u = s_u[t];
                    else {
                        int cc = t / win, r = t % win;
                        u = (r < s_ccnt[cc])
                          ? __float_as_uint(g_keep_score[(img * C_CLS + cc) * MAX_DET + r]) : 0;
                    }
                    if (u && (int)(u >> 22) == b1) atomicAdd(&hist[(u >> 11) & 0x7FF], 1);
                }
                __syncthreads();
                find_cross(hist, 2048, MAX_DET - na1, tid, wtot, s_res);
                __syncthreads();
                int b2 = s_res[0], na2 = s_res[1];
                unsigned p2 = ((unsigned)b1 << 11) | (unsigned)b2;

                for (int i = tid; i < NB; i += TPB) hist[i] = 0;
                __syncthreads();
                for (int t = tid; t < pool; t += TPB) {
                    unsigned u;
                    if (!mode) u = s_u[t];
                    else {
                        int cc = t / win, r = t % win;
                        u = (r < s_ccnt[cc])
                          ? __float_as_uint(g_keep_score[(img * C_CLS + cc) * MAX_DET + r]) : 0;
                    }
                    if (u && (u >> 11) == p2) atomicAdd(&hist[u & 0x7FF], 1);
                }
                __syncthreads();
                find_cross(hist, 2048, MAX_DET - na1 - na2, tid, wtot, s_res);
                __syncthreads();
                Tu = (p2 << 11) | (unsigned)s_res[0];
            }
            __syncthreads();

            if (mode == 0) {
                bool valid = found ? (Tu > s_maxtr) : (s_maxtr == 0);
                if (valid) break;
            }
        }

        // collect all entries >= exact threshold
        for (int t = tid; t < pool; t += TPB) {
            unsigned u;
            int cc = t / win, r = t % win;
            if (!fmode) u = s_u[t];
            else u = (r < s_ccnt[cc])
                   ? __float_as_uint(g_keep_score[(img * C_CLS + cc) * MAX_DET + r]) : 0;
            if (u && (!found || u >= Tu)) {
                int pos = atomicAdd(&s_ncoll, 1);
                if (pos < CCAP) {
                    int flat = cc * MAX_DET + r;
                    s_k3[pos] = ((unsigned long long)u << 16) | (unsigned)(0xFFFF - flat);
                }
            }
        }
        if (tid < MAX_DET) s_sorted[tid] = 0ull;
        __syncthreads();
        int Ncoll = s_ncoll < CCAP ? s_ncoll : CCAP;

        // rank-scatter: unique keys -> rank = #greater; ranks <300 fill contiguously
        for (int i = tid; i < Ncoll; i += TPB) {
            unsigned long long kk = s_k3[i];
            int rank = 0;
            for (int j = 0; j < Ncoll; j++) rank += (s_k3[j] > kk);
            if (rank < MAX_DET) s_sorted[rank] = kk;
        }
        __syncthreads();

        if (tid < MAX_DET) {
            float* fb = out + img * (MAX_DET * 4) + tid * 4;
            float* fs = out + B_IMG * MAX_DET * 4 + img * MAX_DET + tid;
            float* fl = out + B_IMG * MAX_DET * 4 + B_IMG * MAX_DET + img * MAX_DET + tid;
            unsigned long long kk = s_sorted[tid];
            if (kk != 0ull) {
                unsigned u = (unsigned)(kk >> 16);
                int flat = 0xFFFF - (int)(kk & 0xFFFF);
                int cc = flat / MAX_DET, r = flat % MAX_DET;
                int n = g_keep_idx[(img * C_CLS + cc) * MAX_DET + r];
                float4 bb = reinterpret_cast<const float4*>(boxes)[img * N_BOX + n];
                fb[0] = bb.x; fb[1] = bb.y; fb[2] = bb.z; fb[3] = bb.w;
                *fs = __uint_as_float(u);
                *fl = (float)cc;
            } else {
                fb[0] = -1.0f; fb[1] = -1.0f; fb[2] = -1.0f; fb[3] = -1.0f;
                *fs = -1.0f; *fl = -1.0f;
            }
        }
    }
}

// ---------------- host launcher ----------------
extern "C" void kernel_launch(void* const* d_in, const int* in_sizes, int n_in,
                              void* d_out, int out_size) {
    const float* boxes = (const float*)d_in[0];           // [2,20000,4]
    const float* cls   = (const float*)d_in[1];           // [2,20000,80]
    const float* cen   = (const float*)d_in[2];           // [2,20000,1]
    float* out = (float*)d_out;                           // fb(2400) | fs(600) | fl(600)

    cudaFuncSetAttribute(fused_kernel,
                         cudaFuncAttributeMaxDynamicSharedMemorySize, SMEM_BYTES);

    fused_kernel<<<GRID, TPB, SMEM_BYTES>>>(boxes, (const float4*)cls, cen, out);
}